// round 5
// baseline (speedup 1.0000x reference)
#include <cuda_runtime.h>
#include <cuda_bf16.h>

// Problem constants (B=32, S=1024, V=64, H=4096)
#define VOCAB   64
#define HID     4096
#define UOUT    128          // 2*V
#define NBLK    128          // grid size == H-split blocks
#define HCHUNK  (HID / NBLK) // 32
#define ROWS_PER_BLK 256     // 32768 rows / 128 blocks

// Deterministic partial-logits scratch: g_part[t][hc][uq] (float4 u-quads), 4 MB
__device__ float4 g_part[VOCAB * NBLK * (UOUT / 4)];
// Per-(token,half) argmax results: g_amax[t*2 + half]
__device__ int g_amax[2 * VOCAB];
// Grid-barrier counters (zero-init; self-reset at end of every launch)
__device__ int g_c1, g_c2, g_exit;

union F2u { unsigned long long u; float2 f; };

// Packed dual-FMA: d = a*b + d on two fp32 lanes.
__device__ __forceinline__ void ffma2(unsigned long long& d,
                                      const unsigned long long a,
                                      const unsigned long long b) {
    asm("fma.rn.f32x2 %0, %1, %2, %3;" : "=l"(d) : "l"(a), "l"(b), "l"(d));
}

// ---------------------------------------------------------------------------
// Single fused kernel. 128 blocks x 512 threads, all co-resident.
// Phase A: h-split partial logits (identical math to prior rounds) +
//          zero-fill of this block's output slice.
// Barrier1 arrive -> token extraction for this block's 256 rows (overlaps
//          stragglers) -> barrier1 wait.
// Phase B: block b reduces+argmaxes job (t = b>>1, half = b&1) from L2.
// Barrier2 -> build table -> write one 1.0f per row. Reset counters.
// ---------------------------------------------------------------------------
__global__ __launch_bounds__(512, 1)
void fused_kernel(const float*  __restrict__ W1, const float* __restrict__ b1,
                  const float*  __restrict__ W2, const float* __restrict__ b2,
                  const float4* __restrict__ in, float* __restrict__ out) {
    __shared__ float4 nets2[VOCAB * (HCHUNK / 2)];   // 16 KB [t][hb] dup {n,n,n',n'}
    __shared__ float4 w2s  [HCHUNK * (UOUT / 4)];    // 16 KB [h][uq]
    __shared__ float4 partB[32 * 16];                //  8 KB phase-B tree
    __shared__ float  vals[VOCAB];
    __shared__ int    tok_s[ROWS_PER_BLK];           //  1 KB
    __shared__ int    table_s[VOCAB];

    const int b   = blockIdx.x;
    const int tid = threadIdx.x;
    const int h0  = b * HCHUNK;

    // ---------------- Phase A: staging (LDGs first, overlap zero-fill) ------
    const int jt = tid >> 3;           // token 0..63
    const int jf = tid & 7;            // float4 within h-chunk
    const float4 w1v = *reinterpret_cast<const float4*>(W1 + jt * HID + h0 + jf * 4);
    const float4 b1v = *reinterpret_cast<const float4*>(b1 + h0 + jf * 4);
    const float4* __restrict__ w2src = reinterpret_cast<const float4*>(W2 + h0 * UOUT);
    const float4 w2a = w2src[tid];
    const float4 w2b = w2src[tid + 512];

    {   // zero-fill this block's 64 KB output slice
        const float4 z = make_float4(0.f, 0.f, 0.f, 0.f);
        float4* dst = reinterpret_cast<float4*>(out) + b * 4096;
        #pragma unroll
        for (int i = 0; i < 8; ++i) dst[tid + i * 512] = z;
    }

    {   // commit staging to smem
        float n0 = fmaxf(w1v.x + b1v.x, 0.f);
        float n1 = fmaxf(w1v.y + b1v.y, 0.f);
        float n2 = fmaxf(w1v.z + b1v.z, 0.f);
        float n3 = fmaxf(w1v.w + b1v.w, 0.f);
        nets2[jt * 16 + jf * 2 + 0] = make_float4(n0, n0, n1, n1);
        nets2[jt * 16 + jf * 2 + 1] = make_float4(n2, n2, n3, n3);
        w2s[tid]       = w2a;
        w2s[tid + 512] = w2b;
    }
    __syncthreads();

    // ---------------- Phase A: compute 4 tokens x 4 u per thread ------------
    {
        const int uq = tid & 31;
        const int t0 = (tid >> 5) * 4;

        const ulonglong2* __restrict__ n2v = reinterpret_cast<const ulonglong2*>(nets2);
        const ulonglong2* __restrict__ w2v = reinterpret_cast<const ulonglong2*>(w2s);

        unsigned long long acc[4][2];
        #pragma unroll
        for (int t = 0; t < 4; ++t) { acc[t][0] = 0ull; acc[t][1] = 0ull; }

        #pragma unroll
        for (int hb = 0; hb < HCHUNK / 2; ++hb) {
            const ulonglong2 w0 = w2v[(2 * hb)     * 32 + uq];
            const ulonglong2 w1 = w2v[(2 * hb + 1) * 32 + uq];
            #pragma unroll
            for (int t = 0; t < 4; ++t) {
                const ulonglong2 nn = n2v[(t0 + t) * 16 + hb];
                ffma2(acc[t][0], nn.x, w0.x);
                ffma2(acc[t][1], nn.x, w0.y);
                ffma2(acc[t][0], nn.y, w1.x);
                ffma2(acc[t][1], nn.y, w1.y);
            }
        }

        #pragma unroll
        for (int t = 0; t < 4; ++t) {
            F2u a0, a1; a0.u = acc[t][0]; a1.u = acc[t][1];
            g_part[((t0 + t) * NBLK + b) * 32 + uq] =
                make_float4(a0.f.x, a0.f.y, a1.f.x, a1.f.y);
        }
    }

    // ---------------- Barrier 1 arrive --------------------------------------
    __threadfence();
    __syncthreads();               // all g_part stores issued before arrive
    if (tid == 0) atomicAdd(&g_c1, 1);

    // ---------------- Token extraction (overlaps barrier skew) --------------
    {
        const float4* src = in + b * 4096;
        #pragma unroll
        for (int i = 0; i < 8; ++i) {
            const int k = tid + i * 512;
            const float4 v = src[k];
            const int q = k & 15;
            int cand = -1;
            if (v.x > 0.5f) cand = q * 4 + 0;
            if (v.y > 0.5f) cand = q * 4 + 1;
            if (v.z > 0.5f) cand = q * 4 + 2;
            if (v.w > 0.5f) cand = q * 4 + 3;
            if (cand >= 0) tok_s[k >> 4] = cand;
        }
    }

    // ---------------- Barrier 1 wait ----------------------------------------
    if (tid == 0) {
        while (*(volatile int*)&g_c1 < NBLK) __nanosleep(64);
    }
    __syncthreads();
    __threadfence();

    // ---------------- Phase B: job (t, half) = (b>>1, b&1) ------------------
    {
        const int t    = b >> 1;
        const int half = b & 1;
        const int uq_l = tid & 15;                 // 16 u-quads in this half
        const int hg   = tid >> 4;                 // 32 hc-groups of 4
        const int uq   = half * 16 + uq_l;

        float4 s = make_float4(0.f, 0.f, 0.f, 0.f);
        #pragma unroll
        for (int i = 0; i < 4; ++i) {              // fixed ascending order
            const float4 v = g_part[(t * NBLK + hg * 4 + i) * 32 + uq];
            s.x += v.x; s.y += v.y; s.z += v.z; s.w += v.w;
        }
        partB[hg * 16 + uq_l] = s;
        __syncthreads();

        if (tid < 16) {
            float4 a = make_float4(0.f, 0.f, 0.f, 0.f);
            #pragma unroll
            for (int g = 0; g < 32; ++g) {         // fixed ascending order
                const float4 v = partB[g * 16 + tid];
                a.x += v.x; a.y += v.y; a.z += v.z; a.w += v.w;
            }
            const int u0 = half * VOCAB + tid * 4;
            vals[tid * 4 + 0] = a.x + b2[u0 + 0];
            vals[tid * 4 + 1] = a.y + b2[u0 + 1];
            vals[tid * 4 + 2] = a.z + b2[u0 + 2];
            vals[tid * 4 + 3] = a.w + b2[u0 + 3];
        }
        __syncthreads();

        if (tid == 0) {
            // jnp.argmax keeps the FIRST max -> strict '>' comparison.
            int idx = 0; float m = vals[0];
            #pragma unroll
            for (int k = 1; k < VOCAB; ++k) if (vals[k] > m) { m = vals[k]; idx = k; }
            g_amax[t * 2 + half] = idx;
        }
    }

    // ---------------- Barrier 2 ---------------------------------------------
    __threadfence();
    __syncthreads();
    if (tid == 0) {
        atomicAdd(&g_c2, 1);
        while (*(volatile int*)&g_c2 < NBLK) __nanosleep(64);
    }
    __syncthreads();
    __threadfence();

    // ---------------- Phase C: table + one-hot writes -----------------------
    if (tid < VOCAB) {
        const int li = g_amax[tid * 2 + 0];        // loc  (first half)
        const int si = g_amax[tid * 2 + 1];        // scale(second half)
        table_s[tid] = (si * tid + li) & (VOCAB - 1);
    }
    __syncthreads();

    if (tid < ROWS_PER_BLK) {
        out[(b * ROWS_PER_BLK + tid) * VOCAB + table_s[tok_s[tid]]] = 1.0f;
    }

    // ---------------- Reset counters for next graph replay ------------------
    __syncthreads();
    if (tid == 0) {
        const int e = atomicAdd(&g_exit, 1);
        if (e == NBLK - 1) {
            *(volatile int*)&g_c1 = 0;
            *(volatile int*)&g_c2 = 0;
            __threadfence();
            *(volatile int*)&g_exit = 0;
        }
    }
}

// ---------------------------------------------------------------------------
extern "C" void kernel_launch(void* const* d_in, const int* in_sizes, int n_in,
                              void* d_out, int out_size) {
    const float* inputs = nullptr;
    const float* W1 = nullptr;
    const float* b1 = nullptr;
    const float* W2 = nullptr;
    const float* b2 = nullptr;

    for (int i = 0; i < n_in; ++i) {
        switch (in_sizes[i]) {
            case 32 * 1024 * 64: inputs = (const float*)d_in[i]; break; // 2097152
            case 64 * 4096:      W1     = (const float*)d_in[i]; break; // 262144
            case 4096:           b1     = (const float*)d_in[i]; break;
            case 4096 * 128:     W2     = (const float*)d_in[i]; break; // 524288
            case 128:            b2     = (const float*)d_in[i]; break;
            default: break;
        }
    }

    fused_kernel<<<NBLK, 512>>>(W1, b1, W2, b2,
                                reinterpret_cast<const float4*>(inputs),
                                reinterpret_cast<float*>(d_out));
}

// round 6
// speedup vs baseline: 1.1403x; 1.1403x over previous
#include <cuda_runtime.h>
#include <cuda_bf16.h>

// Problem constants (B=32, S=1024, V=64, H=4096)
#define VOCAB   64
#define HID     4096
#define UOUT    128          // 2*V
#define NBLK    128          // H-split blocks
#define HCHUNK  (HID / NBLK) // 32

// Per-token output index table: out_idx[t] = (scale_idx[t]*t + loc_idx[t]) mod 64
__device__ int    g_table[VOCAB];
// Partial logits scratch: part[t][b][uq], float4 u-quads
__device__ float4 g_part[VOCAB * NBLK * (UOUT / 4)];   // 4 MB

union F2u { unsigned long long u; float2 f; };

// Packed dual-FMA: d = a*b + d on two fp32 lanes.
__device__ __forceinline__ void ffma2(unsigned long long& d,
                                      const unsigned long long a,
                                      const unsigned long long b) {
    asm("fma.rn.f32x2 %0, %1, %2, %3;" : "=l"(d) : "l"(a), "l"(b), "l"(d));
}

// ---------------------------------------------------------------------------
// K1: partial logits only (zero-fill removed; K3 now writes full rows).
// Block b owns H-chunk [b*32, b*32+32). 512 threads.
// nets staged pre-duplicated {n,n,n',n'} so one broadcast LDS.128 feeds two
// h-steps of packed FFMA2. Thread (uq, group): u-quad uq, 4 tokens.
// ---------------------------------------------------------------------------
__global__ __launch_bounds__(512, 1)
void partial_kernel(const float* __restrict__ W1, const float* __restrict__ b1,
                    const float* __restrict__ W2) {
    __shared__ float4 nets2[VOCAB * (HCHUNK / 2)];   // 16 KB [t][hb]
    __shared__ float4 w2s  [HCHUNK * (UOUT / 4)];    // 16 KB [h][uq]

    const int b   = blockIdx.x;
    const int tid = threadIdx.x;
    const int h0  = b * HCHUNK;

    // --- staging: all LDGs issued up front ---
    const int jt = tid >> 3;           // token 0..63
    const int jf = tid & 7;            // float4 within h-chunk
    const float4 w1v = *reinterpret_cast<const float4*>(W1 + jt * HID + h0 + jf * 4);
    const float4 b1v = *reinterpret_cast<const float4*>(b1 + h0 + jf * 4);
    const float4* __restrict__ w2src = reinterpret_cast<const float4*>(W2 + h0 * UOUT);
    const float4 w2a = w2src[tid];
    const float4 w2b = w2src[tid + 512];

    {
        float n0 = fmaxf(w1v.x + b1v.x, 0.f);
        float n1 = fmaxf(w1v.y + b1v.y, 0.f);
        float n2 = fmaxf(w1v.z + b1v.z, 0.f);
        float n3 = fmaxf(w1v.w + b1v.w, 0.f);
        nets2[jt * 16 + jf * 2 + 0] = make_float4(n0, n0, n1, n1);
        nets2[jt * 16 + jf * 2 + 1] = make_float4(n2, n2, n3, n3);
        w2s[tid]       = w2a;
        w2s[tid + 512] = w2b;
    }
    __syncthreads();

    const int uq = tid & 31;           // u-quad 0..31
    const int t0 = (tid >> 5) * 4;     // 4 tokens per thread (16 groups)

    const ulonglong2* __restrict__ n2v = reinterpret_cast<const ulonglong2*>(nets2);
    const ulonglong2* __restrict__ w2v = reinterpret_cast<const ulonglong2*>(w2s);

    unsigned long long acc[4][2];
    #pragma unroll
    for (int t = 0; t < 4; ++t) { acc[t][0] = 0ull; acc[t][1] = 0ull; }

    #pragma unroll
    for (int hb = 0; hb < HCHUNK / 2; ++hb) {              // 2 h per step
        const ulonglong2 w0 = w2v[(2 * hb)     * 32 + uq];
        const ulonglong2 w1 = w2v[(2 * hb + 1) * 32 + uq];
        #pragma unroll
        for (int t = 0; t < 4; ++t) {
            const ulonglong2 nn = n2v[(t0 + t) * 16 + hb]; // broadcast
            ffma2(acc[t][0], nn.x, w0.x);
            ffma2(acc[t][1], nn.x, w0.y);
            ffma2(acc[t][0], nn.y, w1.x);
            ffma2(acc[t][1], nn.y, w1.y);
        }
    }

    #pragma unroll
    for (int t = 0; t < 4; ++t) {
        F2u a0, a1; a0.u = acc[t][0]; a1.u = acc[t][1];
        g_part[((t0 + t) * NBLK + b) * 32 + uq] =
            make_float4(a0.f.x, a0.f.y, a1.f.x, a1.f.y);
    }
}

// ---------------------------------------------------------------------------
// K2: reduce partials over the 128 H-blocks, add b2, argmax both halves.
// One block per token, 256 threads (8 warps x 16 b's each).
// ---------------------------------------------------------------------------
__global__ __launch_bounds__(256, 1)
void reduce_kernel(const float* __restrict__ b2) {
    __shared__ float red[8][UOUT];
    __shared__ float logits[UOUT];

    const int t    = blockIdx.x;
    const int tid  = threadIdx.x;
    const int warp = tid >> 5;
    const int lane = tid & 31;

    float4 acc = make_float4(0.f, 0.f, 0.f, 0.f);
    const float4* base = &g_part[(t * NBLK) * 32 + lane];
    #pragma unroll 8
    for (int b = warp * 16; b < warp * 16 + 16; ++b) {
        const float4 v = base[b * 32];
        acc.x += v.x; acc.y += v.y; acc.z += v.z; acc.w += v.w;
    }
    red[warp][lane * 4 + 0] = acc.x;
    red[warp][lane * 4 + 1] = acc.y;
    red[warp][lane * 4 + 2] = acc.z;
    red[warp][lane * 4 + 3] = acc.w;
    __syncthreads();

    if (tid < UOUT) {
        float s = b2[tid];
        #pragma unroll
        for (int w = 0; w < 8; ++w) s += red[w][tid];
        logits[tid] = s;
    }
    __syncthreads();

    if (tid == 0) {
        // jnp.argmax keeps the FIRST max -> strict '>' comparison.
        int   li = 0; float lm = logits[0];
        #pragma unroll
        for (int k = 1; k < VOCAB; ++k) if (logits[k] > lm) { lm = logits[k]; li = k; }
        int   si = 0; float sm = logits[VOCAB];
        #pragma unroll
        for (int k = 1; k < VOCAB; ++k) if (logits[VOCAB + k] > sm) { sm = logits[VOCAB + k]; si = k; }
        // loc = first half, scale = second half (jnp.split order)
        g_table[t] = (si * t + li) & (VOCAB - 1);
    }
}

// ---------------------------------------------------------------------------
// K3: full-row writer, MLP=4. Each thread handles float4 slot q of 4 rows:
// 4 in-flight LDG.128, shfl(width 16) to recover each row's token, then
// writes the complete output float4 (zeros + possible 1.0). Reads 8 MB,
// writes 8 MB, both perfectly coalesced; no pre-zero dependency.
// ---------------------------------------------------------------------------
#define TOTAL_F4 (32 * 1024 * 64 / 4)   // 524288
#define SC_STRIDE (TOTAL_F4 / 4)        // 131072 (multiple of 16 -> same q per k)

__global__ __launch_bounds__(256)
void out_kernel(const float4* __restrict__ in, float4* __restrict__ out) {
    const int base = blockIdx.x * 256 + threadIdx.x;
    const int q    = base & 15;         // same for all k (stride multiple of 16)

    float4 v[4];
    #pragma unroll
    for (int k = 0; k < 4; ++k) v[k] = in[base + k * SC_STRIDE];

    #pragma unroll
    for (int k = 0; k < 4; ++k) {
        int cand = -1;
        if (v[k].x > 0.5f) cand = q * 4 + 0;
        if (v[k].y > 0.5f) cand = q * 4 + 1;
        if (v[k].z > 0.5f) cand = q * 4 + 2;
        if (v[k].w > 0.5f) cand = q * 4 + 3;

        #pragma unroll
        for (int off = 8; off; off >>= 1)
            cand = max(cand, __shfl_xor_sync(0xFFFFFFFFu, cand, off, 16));

        const int oi = g_table[cand];   // uniform broadcast load

        float4 o = make_float4(0.f, 0.f, 0.f, 0.f);
        if ((oi >> 2) == q) reinterpret_cast<float*>(&o)[oi & 3] = 1.0f;
        out[base + k * SC_STRIDE] = o;
    }
}

// ---------------------------------------------------------------------------
extern "C" void kernel_launch(void* const* d_in, const int* in_sizes, int n_in,
                              void* d_out, int out_size) {
    const float* inputs = nullptr;
    const float* W1 = nullptr;
    const float* b1 = nullptr;
    const float* W2 = nullptr;
    const float* b2 = nullptr;

    for (int i = 0; i < n_in; ++i) {
        switch (in_sizes[i]) {
            case 32 * 1024 * 64: inputs = (const float*)d_in[i]; break; // 2097152
            case 64 * 4096:      W1     = (const float*)d_in[i]; break; // 262144
            case 4096:           b1     = (const float*)d_in[i]; break;
            case 4096 * 128:     W2     = (const float*)d_in[i]; break; // 524288
            case 128:            b2     = (const float*)d_in[i]; break;
            default: break;
        }
    }

    partial_kernel<<<NBLK, 512>>>(W1, b1, W2);
    reduce_kernel<<<VOCAB, 256>>>(b2);
    out_kernel<<<SC_STRIDE / 256, 256>>>(
        reinterpret_cast<const float4*>(inputs),
        reinterpret_cast<float4*>(d_out));
}